// round 1
// baseline (speedup 1.0000x reference)
#include <cuda_runtime.h>
#include <math.h>

#define BATCH   32768
#define EMBED   300
#define HIDDEN  300
#define KNEG    10
#define ROWS    64
#define STRIDE  308                  // 300 + 8 pad: 12*r mod 32 distinct over 8 rows, 16B aligned
#define NBLOCKS (BATCH / ROWS)       // 512
#define KDIM    300

__device__ float2 g_partials[NBLOCKS];

// ---------------------------------------------------------------------------
// Tiled SGEMM on smem input: D[r][h] = sum_k S[r][k] * W[h][k] + bias[h]
// S, D are smem [64][STRIDE]; W is global [>=300][300] row-major; 300 cols out.
// Thread layout: ty=tid/16 -> 4 rows each; tx=tid%16 -> 4 cols each; 5 h-tiles.
// ---------------------------------------------------------------------------
__device__ __forceinline__ void gemm_tile(const float* __restrict__ S,
                                          const float* __restrict__ W,
                                          const float* __restrict__ bias,
                                          float* __restrict__ D)
{
    const int tid = threadIdx.x;
    const int ty = tid >> 4;          // 0..15
    const int tx = tid & 15;          // 0..15
    const int row0 = ty * 4;

    #pragma unroll 1
    for (int h0 = 0; h0 < 320; h0 += 64) {
        const int hbase = h0 + tx * 4;
        const float* wp[4];
        #pragma unroll
        for (int j = 0; j < 4; ++j) {
            int hj = hbase + j;
            if (hj > 299) hj = 299;          // clamp: garbage computed, masked on store
            wp[j] = W + hj * KDIM;
        }

        float acc[4][4];
        #pragma unroll
        for (int i = 0; i < 4; ++i)
            #pragma unroll
            for (int j = 0; j < 4; ++j) acc[i][j] = 0.f;

        #pragma unroll 5
        for (int k = 0; k < KDIM; k += 4) {
            float4 a[4], b[4];
            #pragma unroll
            for (int i = 0; i < 4; ++i)
                a[i] = *(const float4*)(S + (row0 + i) * STRIDE + k);
            #pragma unroll
            for (int j = 0; j < 4; ++j)
                b[j] = *(const float4*)(wp[j] + k);
            #pragma unroll
            for (int i = 0; i < 4; ++i)
                #pragma unroll
                for (int j = 0; j < 4; ++j) {
                    acc[i][j] += a[i].x * b[j].x;
                    acc[i][j] += a[i].y * b[j].y;
                    acc[i][j] += a[i].z * b[j].z;
                    acc[i][j] += a[i].w * b[j].w;
                }
        }

        #pragma unroll
        for (int j = 0; j < 4; ++j) {
            const int hj = hbase + j;
            if (hj < 300) {
                const float bv = bias[hj];
                #pragma unroll
                for (int i = 0; i < 4; ++i)
                    D[(row0 + i) * STRIDE + hj] = acc[i][j] + bv;
            }
        }
    }
}

__global__ __launch_bounds__(256) void fused_kernel(
    const int* __restrict__ cen_ids,  const int* __restrict__ ctx_ids,
    const int* __restrict__ neg_ids,  const int* __restrict__ labels,
    const float* __restrict__ cen_emb, const float* __restrict__ ctx_emb,
    const float* __restrict__ W_enc,  const float* __restrict__ b_enc,
    const float* __restrict__ W_dec,  const float* __restrict__ b_dec,
    const float* __restrict__ W_cls,  const float* __restrict__ b_cls)
{
    extern __shared__ float sm[];
    float* sA   = sm;                       // [64][308]  emb -> center_v
    float* sB   = sm + ROWS * STRIDE;       // [64][308]  enc
    float* sRed = sm + 2 * ROWS * STRIDE;   // [32]
    float* sNll = sRed + 32;                // [8]

    const int tid = threadIdx.x;
    const int r0  = blockIdx.x * ROWS;

    // ---- Phase 0: gather center embeddings into smem (float4, coalesced) ----
    for (int idx = tid; idx < ROWS * 75; idx += 256) {
        const int r = idx / 75;
        const int q = idx - r * 75;
        const int wid = cen_ids[r0 + r];
        ((float4*)(sA + r * STRIDE))[q] =
            ((const float4*)(cen_emb + wid * EMBED))[q];
    }
    __syncthreads();

    // ---- Phase 1: enc = emb @ W_enc^T + b_enc ----
    gemm_tile(sA, W_enc, b_enc, sB);
    __syncthreads();

    // ---- Phase 2: center_v = enc @ W_dec^T + b_dec (overwrite sA) ----
    gemm_tile(sB, W_dec, b_dec, sA);
    __syncthreads();

    // ---- Phase 3: pos/neg scores. warp-per-row, 8-lane octet per dot. ----
    const int warp = tid >> 5;
    const int lane = tid & 31;
    const int o    = lane >> 3;   // octet 0..3
    const int l    = lane & 7;    // sublane 0..7

    float accDeno = 0.f;          // valid on l==0 lanes

    #pragma unroll 1
    for (int t = 0; t < 8; ++t) {
        const int r  = warp * 8 + t;
        const int gr = r0 + r;
        const float4* cv = (const float4*)(sA + r * STRIDE);

        #pragma unroll
        for (int round = 0; round < 3; ++round) {
            const int j = round * 4 + o;
            const bool valid = (j < 11);
            int wid = 0;
            if (valid) wid = (j == 0) ? ctx_ids[gr] : neg_ids[gr * KNEG + (j - 1)];
            const float4* xp = (const float4*)(ctx_emb + wid * EMBED);

            float acc = 0.f;
            #pragma unroll
            for (int s = 0; s < 10; ++s) {
                const int e4 = s * 8 + l;
                if (e4 < 75) {
                    const float4 c = cv[e4];
                    const float4 x = xp[e4];
                    acc += c.x * x.x + c.y * x.y + c.z * x.z + c.w * x.w;
                }
            }
            acc += __shfl_down_sync(0xffffffffu, acc, 4, 8);
            acc += __shfl_down_sync(0xffffffffu, acc, 2, 8);
            acc += __shfl_down_sync(0xffffffffu, acc, 1, 8);

            if (l == 0 && valid) {
                float s1 = fminf(fmaxf(acc, -10.f), 10.f);
                // j==0: -logsigmoid(s) = log1p(exp(-s)); j>0: -logsigmoid(-s) = log1p(exp(s))
                accDeno += (j == 0) ? log1pf(__expf(-s1)) : log1pf(__expf(s1));
            }
        }
    }

    // ---- Phase 4: logits + NLL. octets 0/1 compute the two logits. ----
    float accNll = 0.f;           // valid on lane==0

    #pragma unroll 1
    for (int t = 0; t < 8; ++t) {
        const int r  = warp * 8 + t;
        const int gr = r0 + r;
        const float4* ev = (const float4*)(sB + r * STRIDE);

        float acc = 0.f;
        if (o < 2) {
            const float4* wp = (const float4*)(W_cls + o * HIDDEN);
            #pragma unroll
            for (int s = 0; s < 10; ++s) {
                const int e4 = s * 8 + l;
                if (e4 < 75) {
                    const float4 c = ev[e4];
                    const float4 x = wp[e4];
                    acc += c.x * x.x + c.y * x.y + c.z * x.z + c.w * x.w;
                }
            }
        }
        acc += __shfl_down_sync(0xffffffffu, acc, 4, 8);
        acc += __shfl_down_sync(0xffffffffu, acc, 2, 8);
        acc += __shfl_down_sync(0xffffffffu, acc, 1, 8);
        const float lg1r = __shfl_sync(0xffffffffu, acc, 8);  // octet 1's reduced value

        if (lane == 0) {
            const float lg0 = acc  + b_cls[0];
            const float lg1 = lg1r + b_cls[1];
            const float m   = fmaxf(lg0, lg1);
            const float lse = m + log1pf(__expf(fminf(lg0, lg1) - m));
            const int lab   = labels[gr];
            accNll += lse - (lab ? lg1 : lg0);
        }
    }

    if (l == 0)    sRed[warp * 4 + o] = accDeno;
    if (lane == 0) sNll[warp]         = accNll;
    __syncthreads();

    // ---- Fixed-order block reduction (deterministic, no atomics) ----
    if (tid == 0) {
        float sd = 0.f, sn = 0.f;
        #pragma unroll
        for (int i = 0; i < 32; ++i) sd += sRed[i];
        #pragma unroll
        for (int i = 0; i < 8;  ++i) sn += sNll[i];
        g_partials[blockIdx.x] = make_float2(sd, sn);
    }
}

__global__ __launch_bounds__(256) void finalize_kernel(float* __restrict__ out)
{
    __shared__ float sd[256], sn[256];
    const int t = threadIdx.x;
    const float2 p0 = g_partials[t];
    const float2 p1 = g_partials[t + 256];
    sd[t] = p0.x + p1.x;
    sn[t] = p0.y + p1.y;
    __syncthreads();
    for (int ofs = 128; ofs > 0; ofs >>= 1) {
        if (t < ofs) { sd[t] += sd[t + ofs]; sn[t] += sn[t + ofs]; }
        __syncthreads();
    }
    if (t == 0) {
        const float invB = 1.0f / (float)BATCH;
        float deno = sd[0] * invB;
        deno = fminf(fmaxf(deno, 1e-5f), 10.f);
        float cono = sn[0] * invB;
        cono = fminf(fmaxf(cono, 1e-5f), 10.f);
        const float enc = fmaxf(deno + cono, 1e-5f);
        out[0] = enc;
        out[1] = deno;
        out[2] = cono;
    }
}

extern "C" void kernel_launch(void* const* d_in, const int* in_sizes, int n_in,
                              void* d_out, int out_size)
{
    const int*   cen_ids = (const int*)  d_in[0];
    const int*   ctx_ids = (const int*)  d_in[1];
    const int*   neg_ids = (const int*)  d_in[2];
    const int*   labels  = (const int*)  d_in[3];
    const float* cen_emb = (const float*)d_in[4];
    const float* ctx_emb = (const float*)d_in[5];
    const float* W_enc   = (const float*)d_in[6];
    const float* b_enc   = (const float*)d_in[7];
    const float* W_dec   = (const float*)d_in[8];
    const float* b_dec   = (const float*)d_in[9];
    const float* W_cls   = (const float*)d_in[10];
    const float* b_cls   = (const float*)d_in[11];

    const size_t smemSize = (size_t)(2 * ROWS * STRIDE + 64) * sizeof(float);
    cudaFuncSetAttribute(fused_kernel,
                         cudaFuncAttributeMaxDynamicSharedMemorySize,
                         (int)smemSize);

    fused_kernel<<<NBLOCKS, 256, smemSize>>>(
        cen_ids, ctx_ids, neg_ids, labels, cen_emb, ctx_emb,
        W_enc, b_enc, W_dec, b_dec, W_cls, b_cls);
    finalize_kernel<<<1, 256>>>((float*)d_out);
}

// round 2
// speedup vs baseline: 1.8610x; 1.8610x over previous
#include <cuda_runtime.h>
#include <math.h>

#define BATCH   32768
#define EMBED   300
#define HIDDEN  300
#define KNEG    10
#define ROWS    64
#define STRIDE  308                  // floats per smem row (16B aligned)
#define NBLOCKS (BATCH / ROWS)       // 512
#define KDIM    300
#define THREADS 512

__device__ float2 g_partials[NBLOCKS];
__device__ float  g_WencT[KDIM * KDIM];   // Wt[k][h] = W_enc[h][k]
__device__ float  g_WdecT[KDIM * KDIM];   // Wt[k][h] = W_dec[h][k]

// ---------------------------------------------------------------------------
// Transpose 300x300: coalesced reads, scattered writes (writes don't stall).
// ---------------------------------------------------------------------------
__global__ __launch_bounds__(256) void transpose_kernel(float* __restrict__ dst,
                                                        const float* __restrict__ src)
{
    const int idx = blockIdx.x * 256 + threadIdx.x;     // over src [h][k]
    if (idx < KDIM * KDIM) {
        const int h = idx / KDIM;
        const int k = idx - h * KDIM;
        dst[k * KDIM + h] = src[idx];
    }
}

__device__ __forceinline__ float get_comp(float4 v, int i)
{
    return (i == 0) ? v.x : (i == 1) ? v.y : (i == 2) ? v.z : v.w;
}

// ---------------------------------------------------------------------------
// Tiled SGEMM, 512 threads: D[r][h] = sum_k S[r][k] * Wt[k][h] + bias[h]
// S, D smem [64][STRIDE]; Wt global [300][300] (k-major, h contiguous).
// ty = tid>>5 (16) -> 4 rows; tx = tid&31 -> 4 contiguous cols; 3 h-tiles of 128.
// a-loads: broadcast LDS.128. b-loads: coalesced LDG.128, L1-resident across warps.
// ---------------------------------------------------------------------------
__device__ __forceinline__ void gemm_tile(const float* __restrict__ S,
                                          const float* __restrict__ Wt,
                                          const float* __restrict__ bias,
                                          float* __restrict__ D)
{
    const int tid  = threadIdx.x;
    const int ty   = tid >> 5;          // 0..15
    const int tx   = tid & 31;          // 0..31
    const int row0 = ty * 4;

    #pragma unroll 1
    for (int h0 = 0; h0 < 384; h0 += 128) {
        const int  h     = h0 + tx * 4;
        const bool valid = (h < KDIM);          // last valid start is 296
        const int  hc    = valid ? h : 296;     // clamp (garbage computed, masked)

        float acc[4][4];
        #pragma unroll
        for (int i = 0; i < 4; ++i)
            #pragma unroll
            for (int j = 0; j < 4; ++j) acc[i][j] = 0.f;

        #pragma unroll 5
        for (int k = 0; k < KDIM; k += 4) {
            float4 A[4];
            #pragma unroll
            for (int i = 0; i < 4; ++i)
                A[i] = *(const float4*)(S + (row0 + i) * STRIDE + k);

            #pragma unroll
            for (int kk = 0; kk < 4; ++kk) {
                const float4 b = *(const float4*)(Wt + (k + kk) * KDIM + hc);
                #pragma unroll
                for (int i = 0; i < 4; ++i) {
                    const float av = get_comp(A[i], kk);
                    acc[i][0] += av * b.x;
                    acc[i][1] += av * b.y;
                    acc[i][2] += av * b.z;
                    acc[i][3] += av * b.w;
                }
            }
        }

        if (valid) {
            const float4 bv = *(const float4*)(bias + hc);
            #pragma unroll
            for (int i = 0; i < 4; ++i) {
                float4 o;
                o.x = acc[i][0] + bv.x;
                o.y = acc[i][1] + bv.y;
                o.z = acc[i][2] + bv.z;
                o.w = acc[i][3] + bv.w;
                *(float4*)(D + (row0 + i) * STRIDE + h) = o;
            }
        }
    }
}

__global__ __launch_bounds__(THREADS) void fused_kernel(
    const int* __restrict__ cen_ids,  const int* __restrict__ ctx_ids,
    const int* __restrict__ neg_ids,  const int* __restrict__ labels,
    const float* __restrict__ cen_emb, const float* __restrict__ ctx_emb,
    const float* __restrict__ b_enc,  const float* __restrict__ b_dec,
    const float* __restrict__ W_cls,  const float* __restrict__ b_cls)
{
    extern __shared__ float sm[];
    float* sA   = sm;                       // [64][308]  emb -> center_v
    float* sB   = sm + ROWS * STRIDE;       // [64][308]  enc
    float* sRed = sm + 2 * ROWS * STRIDE;   // [64] deno partials
    float* sNll = sRed + 64;                // [16] nll partials

    const int tid = threadIdx.x;
    const int r0  = blockIdx.x * ROWS;

    // ---- Phase 0: gather center embeddings into smem (float4, coalesced) ----
    for (int idx = tid; idx < ROWS * 75; idx += THREADS) {
        const int r = idx / 75;
        const int q = idx - r * 75;
        const int wid = cen_ids[r0 + r];
        ((float4*)(sA + r * STRIDE))[q] =
            ((const float4*)(cen_emb + wid * EMBED))[q];
    }
    __syncthreads();

    // ---- Phase 1: enc = emb @ W_enc^T + b_enc ----
    gemm_tile(sA, g_WencT, b_enc, sB);
    __syncthreads();

    // ---- Phase 2: center_v = enc @ W_dec^T + b_dec (overwrite sA) ----
    gemm_tile(sB, g_WdecT, b_dec, sA);
    __syncthreads();

    // ---- Phase 3: pos/neg scores. warp handles 4 rows; 8-lane octet per dot ----
    const int warp = tid >> 5;          // 0..15
    const int lane = tid & 31;
    const int o    = lane >> 3;         // octet 0..3
    const int l    = lane & 7;          // sublane 0..7

    float accDeno = 0.f;                // valid on l==0 lanes

    #pragma unroll 1
    for (int t = 0; t < 4; ++t) {
        const int r  = warp * 4 + t;
        const int gr = r0 + r;
        const float4* cv = (const float4*)(sA + r * STRIDE);

        #pragma unroll
        for (int round = 0; round < 3; ++round) {
            const int j = round * 4 + o;
            const bool valid = (j < 11);
            int wid = 0;
            if (valid) wid = (j == 0) ? ctx_ids[gr] : neg_ids[gr * KNEG + (j - 1)];
            const float4* xp = (const float4*)(ctx_emb + wid * EMBED);

            float acc = 0.f;
            #pragma unroll
            for (int s = 0; s < 10; ++s) {
                const int e4 = s * 8 + l;
                if (e4 < 75) {
                    const float4 c = cv[e4];
                    const float4 x = xp[e4];
                    acc += c.x * x.x + c.y * x.y + c.z * x.z + c.w * x.w;
                }
            }
            acc += __shfl_down_sync(0xffffffffu, acc, 4, 8);
            acc += __shfl_down_sync(0xffffffffu, acc, 2, 8);
            acc += __shfl_down_sync(0xffffffffu, acc, 1, 8);

            if (l == 0 && valid) {
                float s1 = fminf(fmaxf(acc, -10.f), 10.f);
                accDeno += (j == 0) ? log1pf(__expf(-s1)) : log1pf(__expf(s1));
            }
        }
    }

    // ---- Phase 4: logits + NLL. octets 0/1 compute the two logits ----
    float accNll = 0.f;                 // valid on lane==0

    #pragma unroll 1
    for (int t = 0; t < 4; ++t) {
        const int r  = warp * 4 + t;
        const int gr = r0 + r;
        const float4* ev = (const float4*)(sB + r * STRIDE);

        float acc = 0.f;
        if (o < 2) {
            const float4* wp = (const float4*)(W_cls + o * HIDDEN);
            #pragma unroll
            for (int s = 0; s < 10; ++s) {
                const int e4 = s * 8 + l;
                if (e4 < 75) {
                    const float4 c = ev[e4];
                    const float4 x = wp[e4];
                    acc += c.x * x.x + c.y * x.y + c.z * x.z + c.w * x.w;
                }
            }
        }
        acc += __shfl_down_sync(0xffffffffu, acc, 4, 8);
        acc += __shfl_down_sync(0xffffffffu, acc, 2, 8);
        acc += __shfl_down_sync(0xffffffffu, acc, 1, 8);
        const float lg1r = __shfl_sync(0xffffffffu, acc, 8);  // octet 1, l==0

        if (lane == 0) {
            const float lg0 = acc  + b_cls[0];
            const float lg1 = lg1r + b_cls[1];
            const float m   = fmaxf(lg0, lg1);
            const float lse = m + log1pf(__expf(fminf(lg0, lg1) - m));
            const int lab   = labels[gr];
            accNll += lse - (lab ? lg1 : lg0);
        }
    }

    if (l == 0)    sRed[warp * 4 + o] = accDeno;
    if (lane == 0) sNll[warp]         = accNll;
    __syncthreads();

    // ---- Fixed-order block reduction (deterministic, no atomics) ----
    if (tid == 0) {
        float sd = 0.f, sn = 0.f;
        #pragma unroll
        for (int i = 0; i < 64; ++i) sd += sRed[i];
        #pragma unroll
        for (int i = 0; i < 16; ++i) sn += sNll[i];
        g_partials[blockIdx.x] = make_float2(sd, sn);
    }
}

__global__ __launch_bounds__(256) void finalize_kernel(float* __restrict__ out)
{
    __shared__ float sd[256], sn[256];
    const int t = threadIdx.x;
    const float2 p0 = g_partials[t];
    const float2 p1 = g_partials[t + 256];
    sd[t] = p0.x + p1.x;
    sn[t] = p0.y + p1.y;
    __syncthreads();
    for (int ofs = 128; ofs > 0; ofs >>= 1) {
        if (t < ofs) { sd[t] += sd[t + ofs]; sn[t] += sn[t + ofs]; }
        __syncthreads();
    }
    if (t == 0) {
        const float invB = 1.0f / (float)BATCH;
        float deno = sd[0] * invB;
        deno = fminf(fmaxf(deno, 1e-5f), 10.f);
        float cono = sn[0] * invB;
        cono = fminf(fmaxf(cono, 1e-5f), 10.f);
        const float enc = fmaxf(deno + cono, 1e-5f);
        out[0] = enc;
        out[1] = deno;
        out[2] = cono;
    }
}

extern "C" void kernel_launch(void* const* d_in, const int* in_sizes, int n_in,
                              void* d_out, int out_size)
{
    const int*   cen_ids = (const int*)  d_in[0];
    const int*   ctx_ids = (const int*)  d_in[1];
    const int*   neg_ids = (const int*)  d_in[2];
    const int*   labels  = (const int*)  d_in[3];
    const float* cen_emb = (const float*)d_in[4];
    const float* ctx_emb = (const float*)d_in[5];
    const float* W_enc   = (const float*)d_in[6];
    const float* b_enc   = (const float*)d_in[7];
    const float* W_dec   = (const float*)d_in[8];
    const float* b_dec   = (const float*)d_in[9];
    const float* W_cls   = (const float*)d_in[10];
    const float* b_cls   = (const float*)d_in[11];

    float* wencT;  cudaGetSymbolAddress((void**)&wencT, g_WencT);
    float* wdecT;  cudaGetSymbolAddress((void**)&wdecT, g_WdecT);

    const int tBlocks = (KDIM * KDIM + 255) / 256;
    transpose_kernel<<<tBlocks, 256>>>(wencT, W_enc);
    transpose_kernel<<<tBlocks, 256>>>(wdecT, W_dec);

    const size_t smemSize = (size_t)(2 * ROWS * STRIDE + 96) * sizeof(float);
    cudaFuncSetAttribute(fused_kernel,
                         cudaFuncAttributeMaxDynamicSharedMemorySize,
                         (int)smemSize);

    fused_kernel<<<NBLOCKS, THREADS, smemSize>>>(
        cen_ids, ctx_ids, neg_ids, labels, cen_emb, ctx_emb,
        b_enc, b_dec, W_cls, b_cls);
    finalize_kernel<<<1, 256>>>((float*)d_out);
}

// round 5
// speedup vs baseline: 5.5185x; 2.9654x over previous
#include <cuda_runtime.h>
#include <cuda_bf16.h>
#include <math.h>
#include <stdint.h>

#define BATCH   32768
#define ROWS    128
#define NBLK    (BATCH / ROWS)      // 256
#define EMBED   300
#define KNEG    10
#define KPAD    320
#define THREADS 256
#define ROWB    656                 // smem row pitch bytes (328 bf16): +16B bank rotation

// ---- smem byte layout ----
// misc floats: NLL[128] @0, DENO[32] @128, WCLS[640] @160, BENC[320] @800, BDEC[320] @1120
#define SMF_NLL   0
#define SMF_DENO  128
#define SMF_WCLS  160
#define SMF_BENC  800
#define SMF_BDEC  1120
#define SMB_A     6144
#define SMB_A2    (SMB_A  + 128 * ROWB)       // 90112
#define SMB_B     (SMB_A2 + 128 * ROWB)       // 174080
#define SM_TOTAL  (SMB_B  + 64 * ROWB)        // 216064

__device__ __nv_bfloat16 g_Wenc[KPAD * KPAD];   // [h][k] row-major, zero padded
__device__ __nv_bfloat16 g_Wdec[KPAD * KPAD];
__device__ float2 g_partials[NBLK];

__device__ __forceinline__ uint32_t smem_u32(const void* p) {
    uint32_t a;
    asm("{ .reg .u64 t; cvta.to.shared.u64 t, %1; cvt.u32.u64 %0, t; }" : "=r"(a) : "l"(p));
    return a;
}

__device__ __forceinline__ void ldsm_x4(uint32_t* r, uint32_t addr) {
    asm volatile("ldmatrix.sync.aligned.m8n8.x4.shared.b16 {%0,%1,%2,%3}, [%4];"
                 : "=r"(r[0]), "=r"(r[1]), "=r"(r[2]), "=r"(r[3]) : "r"(addr));
}

__device__ __forceinline__ void mma_bf16(float* d, const uint32_t* a, const uint32_t* b) {
    asm volatile("mma.sync.aligned.m16n8k16.row.col.f32.bf16.bf16.f32 "
                 "{%0,%1,%2,%3},{%4,%5,%6,%7},{%8,%9},{%0,%1,%2,%3};"
                 : "+f"(d[0]), "+f"(d[1]), "+f"(d[2]), "+f"(d[3])
                 : "r"(a[0]), "r"(a[1]), "r"(a[2]), "r"(a[3]), "r"(b[0]), "r"(b[1]));
}

// ---------------------------------------------------------------------------
// Weight convert: fp32 [300][300] -> bf16 [320][320] row-major, zero-padded
// ---------------------------------------------------------------------------
__global__ __launch_bounds__(256) void convert_w(__nv_bfloat16* __restrict__ dst,
                                                 const float* __restrict__ src)
{
    const int idx = blockIdx.x * 256 + threadIdx.x;
    if (idx >= KPAD * KPAD) return;
    const int h = idx / KPAD;
    const int k = idx - h * KPAD;
    dst[idx] = __float2bfloat16((h < 300 && k < 300) ? src[h * 300 + k] : 0.f);
}

// ---------------------------------------------------------------------------
// Fused main kernel
// ---------------------------------------------------------------------------
__global__ __launch_bounds__(THREADS) void fused_kernel(
    const int* __restrict__ cen_ids,  const int* __restrict__ ctx_ids,
    const int* __restrict__ neg_ids,  const int* __restrict__ labels,
    const float* __restrict__ cen_emb, const float* __restrict__ ctx_emb,
    const float* __restrict__ b_enc,  const float* __restrict__ b_dec,
    const float* __restrict__ W_cls,  const float* __restrict__ b_cls)
{
    extern __shared__ char smc[];
    float* smf = (float*)smc;
    const uint32_t sb = smem_u32(smc);
    const int tid  = threadIdx.x;
    const int wid  = tid >> 5;
    const int lane = tid & 31;
    const int r0   = blockIdx.x * ROWS;

    // ---- Phase 0: constants + gather emb -> bf16 A tile ----
    for (int i = tid; i < 640; i += THREADS) {
        const int cls = i / KPAD, col = i - cls * KPAD;
        smf[SMF_WCLS + i] = (col < 300) ? W_cls[cls * 300 + col] : 0.f;
    }
    for (int i = tid; i < KPAD; i += THREADS) {
        smf[SMF_BENC + i] = (i < 300) ? b_enc[i] : 0.f;
        smf[SMF_BDEC + i] = (i < 300) ? b_dec[i] : 0.f;
    }
    for (int idx = tid; idx < ROWS * (KPAD / 2); idx += THREADS) {
        const int r = idx / (KPAD / 2);
        const int c = (idx - r * (KPAD / 2)) * 2;
        float2 v = make_float2(0.f, 0.f);
        if (c < 300)
            v = *(const float2*)(cen_emb + (size_t)cen_ids[r0 + r] * EMBED + c);
        *(__nv_bfloat162*)(smc + SMB_A + r * ROWB + c * 2) = __floats2bfloat162_rn(v.x, v.y);
    }
    __syncthreads();

    const int m0 = wid * 16;
    const int rowA = m0 + (lane >> 2);          // rowB = rowA + 8
    const int cq   = (lane & 3) * 2;            // col offset within n-tile
    float lg00 = 0.f, lg01 = 0.f, lg10 = 0.f, lg11 = 0.f;

    // ================= two chained GEMMs =================
    #pragma unroll 1
    for (int g = 0; g < 2; ++g) {
        const __nv_bfloat16* gW = g ? g_Wdec : g_Wenc;
        const uint32_t aBase = sb + (g ? SMB_A2 : SMB_A);
        // ldmatrix A address for this lane (row = m0 + lane%16, khalf = lane/16)
        const uint32_t aAddr0 = aBase + (uint32_t)(m0 + (lane & 15)) * ROWB
                              + (uint32_t)((lane >> 4) * 8) * 2;
        // ldmatrix B address pieces: n_local = (lane/16)*8 + lane%8, khalf2 = (lane/8)&1
        const uint32_t bAddr0 = sb + SMB_B
                              + (uint32_t)(((lane >> 4) << 3) + (lane & 7)) * ROWB
                              + (uint32_t)(((lane >> 3) & 1) * 8) * 2;

        #pragma unroll 1
        for (int chunk = 0; chunk < 5; ++chunk) {
            const int n0 = chunk * 64;
            // ---- stream B chunk: W rows n0..n0+63, 320 cols, into padded smem ----
            {
                const uint4* src = (const uint4*)(gW + (size_t)n0 * KPAD);
                for (int i = tid; i < 64 * 40; i += THREADS) {
                    const int r = i / 40, q = i - r * 40;
                    *(uint4*)(smc + SMB_B + r * ROWB + q * 16) = src[r * 40 + q];
                }
            }
            __syncthreads();

            float acc[8][4];
            #pragma unroll
            for (int j = 0; j < 8; ++j)
                #pragma unroll
                for (int i = 0; i < 4; ++i) acc[j][i] = 0.f;

            #pragma unroll 4
            for (int ks = 0; ks < 20; ++ks) {
                uint32_t a[4];
                ldsm_x4(a, aAddr0 + ks * 32);
                #pragma unroll
                for (int jt = 0; jt < 4; ++jt) {
                    uint32_t b[4];
                    ldsm_x4(b, bAddr0 + jt * 16 * ROWB + ks * 32);
                    mma_bf16(acc[2 * jt],     a, b);
                    mma_bf16(acc[2 * jt + 1], a, b + 2);
                }
            }

            // ---- epilogue for this chunk (in-register) ----
            if (g == 0) {
                #pragma unroll
                for (int j = 0; j < 8; ++j) {
                    const int c0 = n0 + 8 * j + cq;
                    const float be0 = smf[SMF_BENC + c0], be1 = smf[SMF_BENC + c0 + 1];
                    const float v0 = acc[j][0] + be0, v1 = acc[j][1] + be1;
                    const float v2 = acc[j][2] + be0, v3 = acc[j][3] + be1;
                    const float w00 = smf[SMF_WCLS + c0],       w01 = smf[SMF_WCLS + c0 + 1];
                    const float w10 = smf[SMF_WCLS + 320 + c0], w11 = smf[SMF_WCLS + 320 + c0 + 1];
                    lg00 += v0 * w00 + v1 * w01;  lg01 += v0 * w10 + v1 * w11;
                    lg10 += v2 * w00 + v3 * w01;  lg11 += v2 * w10 + v3 * w11;
                    *(__nv_bfloat162*)(smc + SMB_A2 + rowA * ROWB + c0 * 2) =
                        __floats2bfloat162_rn(v0, v1);
                    *(__nv_bfloat162*)(smc + SMB_A2 + (rowA + 8) * ROWB + c0 * 2) =
                        __floats2bfloat162_rn(v2, v3);
                }
            } else {
                #pragma unroll
                for (int j = 0; j < 8; ++j) {
                    const int c0 = n0 + 8 * j + cq;
                    const float bd0 = smf[SMF_BDEC + c0], bd1 = smf[SMF_BDEC + c0 + 1];
                    *(__nv_bfloat162*)(smc + SMB_A + rowA * ROWB + c0 * 2) =
                        __floats2bfloat162_rn(acc[j][0] + bd0, acc[j][1] + bd1);
                    *(__nv_bfloat162*)(smc + SMB_A + (rowA + 8) * ROWB + c0 * 2) =
                        __floats2bfloat162_rn(acc[j][2] + bd0, acc[j][3] + bd1);
                }
            }
            __syncthreads();
        }

        if (g == 0) {
            // finish logits: reduce over quad lanes (fixed order, deterministic)
            lg00 += __shfl_xor_sync(0xffffffffu, lg00, 1);
            lg00 += __shfl_xor_sync(0xffffffffu, lg00, 2);
            lg01 += __shfl_xor_sync(0xffffffffu, lg01, 1);
            lg01 += __shfl_xor_sync(0xffffffffu, lg01, 2);
            lg10 += __shfl_xor_sync(0xffffffffu, lg10, 1);
            lg10 += __shfl_xor_sync(0xffffffffu, lg10, 2);
            lg11 += __shfl_xor_sync(0xffffffffu, lg11, 1);
            lg11 += __shfl_xor_sync(0xffffffffu, lg11, 2);
            if ((lane & 3) == 0) {
                const float bc0 = b_cls[0], bc1 = b_cls[1];
                {
                    const float l0 = lg00 + bc0, l1 = lg01 + bc1;
                    const float m  = fmaxf(l0, l1);
                    const float lse = m + log1pf(__expf(fminf(l0, l1) - m));
                    smf[SMF_NLL + rowA] = lse - (labels[r0 + rowA] ? l1 : l0);
                }
                {
                    const float l0 = lg10 + bc0, l1 = lg11 + bc1;
                    const float m  = fmaxf(l0, l1);
                    const float lse = m + log1pf(__expf(fminf(l0, l1) - m));
                    smf[SMF_NLL + rowA + 8] = lse - (labels[r0 + rowA + 8] ? l1 : l0);
                }
            }
            __syncthreads();
        }
    }

    // ---- Phase 3: pos/neg dots vs gathered ctx_emb (cv bf16 in A region) ----
    const int o = lane >> 3;
    const int l = lane & 7;
    float accDeno = 0.f;

    #pragma unroll 1
    for (int t = 0; t < 16; ++t) {
        const int r  = wid * 16 + t;
        const int gr = r0 + r;
        const char* cvp = smc + SMB_A + r * ROWB;

        #pragma unroll
        for (int round = 0; round < 3; ++round) {
            const int j = round * 4 + o;
            const bool valid = (j < 11);
            int widx = 0;
            if (valid) widx = (j == 0) ? ctx_ids[gr] : neg_ids[gr * KNEG + (j - 1)];
            const float4* xp = (const float4*)(ctx_emb + (size_t)widx * EMBED);

            float acc = 0.f;
            #pragma unroll
            for (int s = 0; s < 10; ++s) {
                const int e4 = s * 8 + l;
                if (e4 < 75) {
                    const uint2 u = *(const uint2*)(cvp + e4 * 8);
                    const float2 p0 = __bfloat1622float2(*(const __nv_bfloat162*)&u.x);
                    const float2 p1 = __bfloat1622float2(*(const __nv_bfloat162*)&u.y);
                    const float4 x = xp[e4];
                    acc += p0.x * x.x + p0.y * x.y + p1.x * x.z + p1.y * x.w;
                }
            }
            acc += __shfl_down_sync(0xffffffffu, acc, 4, 8);
            acc += __shfl_down_sync(0xffffffffu, acc, 2, 8);
            acc += __shfl_down_sync(0xffffffffu, acc, 1, 8);

            if (l == 0 && valid) {
                const float s1 = fminf(fmaxf(acc, -10.f), 10.f);
                accDeno += (j == 0) ? log1pf(__expf(-s1)) : log1pf(__expf(s1));
            }
        }
    }
    if (l == 0) smf[SMF_DENO + wid * 4 + o] = accDeno;
    __syncthreads();

    // ---- fixed-order block reduction ----
    if (tid == 0) {
        float sd = 0.f, sn = 0.f;
        #pragma unroll
        for (int i = 0; i < 32;  ++i) sd += smf[SMF_DENO + i];
        #pragma unroll
        for (int i = 0; i < 128; ++i) sn += smf[SMF_NLL + i];
        g_partials[blockIdx.x] = make_float2(sd, sn);
    }
}

__global__ __launch_bounds__(256) void finalize_kernel(float* __restrict__ out)
{
    __shared__ float sd[256], sn[256];
    const int t = threadIdx.x;
    const float2 p = g_partials[t];
    sd[t] = p.x;  sn[t] = p.y;
    __syncthreads();
    for (int ofs = 128; ofs > 0; ofs >>= 1) {
        if (t < ofs) { sd[t] += sd[t + ofs]; sn[t] += sn[t + ofs]; }
        __syncthreads();
    }
    if (t == 0) {
        const float invB = 1.0f / (float)BATCH;
        float deno = fminf(fmaxf(sd[0] * invB, 1e-5f), 10.f);
        float cono = fminf(fmaxf(sn[0] * invB, 1e-5f), 10.f);
        out[0] = fmaxf(deno + cono, 1e-5f);
        out[1] = deno;
        out[2] = cono;
    }
}

extern "C" void kernel_launch(void* const* d_in, const int* in_sizes, int n_in,
                              void* d_out, int out_size)
{
    const int*   cen_ids = (const int*)  d_in[0];
    const int*   ctx_ids = (const int*)  d_in[1];
    const int*   neg_ids = (const int*)  d_in[2];
    const int*   labels  = (const int*)  d_in[3];
    const float* cen_emb = (const float*)d_in[4];
    const float* ctx_emb = (const float*)d_in[5];
    const float* W_enc   = (const float*)d_in[6];
    const float* b_enc   = (const float*)d_in[7];
    const float* W_dec   = (const float*)d_in[8];
    const float* b_dec   = (const float*)d_in[9];
    const float* W_cls   = (const float*)d_in[10];
    const float* b_cls   = (const float*)d_in[11];

    __nv_bfloat16* we;  cudaGetSymbolAddress((void**)&we, g_Wenc);
    __nv_bfloat16* wd;  cudaGetSymbolAddress((void**)&wd, g_Wdec);

    const int cBlocks = (KPAD * KPAD + 255) / 256;
    convert_w<<<cBlocks, 256>>>(we, W_enc);
    convert_w<<<cBlocks, 256>>>(wd, W_dec);

    cudaFuncSetAttribute(fused_kernel,
                         cudaFuncAttributeMaxDynamicSharedMemorySize, SM_TOTAL);
    fused_kernel<<<NBLK, THREADS, SM_TOTAL>>>(
        cen_ids, ctx_ids, neg_ids, labels, cen_emb, ctx_emb,
        b_enc, b_dec, W_cls, b_cls);
    finalize_kernel<<<1, 256>>>((float*)d_out);
}

// round 6
// speedup vs baseline: 7.5452x; 1.3672x over previous
#include <cuda_runtime.h>
#include <cuda_bf16.h>
#include <math.h>
#include <stdint.h>

#define BATCH   32768
#define ROWS    128
#define NBLK    (BATCH / ROWS)      // 256
#define EMBED   300
#define KNEG    10
#define KPAD    320
#define THREADS 512
#define ROWB    656                 // smem row pitch bytes (328 bf16): +16B bank rotation

// ---- smem float-index layout for misc block ----
#define SMF_NLL   0                  // 128
#define SMF_DENO  128                // 64
#define SMF_WCLS  192                // 640
#define SMF_BENC  832                // 320
#define SMF_BDEC  1152               // 320
#define SMF_LGP   1472               // 256 (nhalf=0 partial logits [128][2])
#define SMF_LGQ   1728               // 256 (nhalf=1)
// ---- smem byte layout ----
#define SMB_A     8192
#define SMB_A2    (SMB_A  + 128 * ROWB)       // 92160
#define SMB_B     (SMB_A2 + 128 * ROWB)       // 176128
#define SM_TOTAL  (SMB_B  + 64 * ROWB)        // 218112

__device__ __nv_bfloat16 g_Wenc[KPAD * KPAD];   // [h][k] row-major, zero padded
__device__ __nv_bfloat16 g_Wdec[KPAD * KPAD];
__device__ float2 g_partials[NBLK];

__device__ __forceinline__ uint32_t smem_u32(const void* p) {
    uint32_t a;
    asm("{ .reg .u64 t; cvta.to.shared.u64 t, %1; cvt.u32.u64 %0, t; }" : "=r"(a) : "l"(p));
    return a;
}

__device__ __forceinline__ void ldsm_x4(uint32_t* r, uint32_t addr) {
    asm volatile("ldmatrix.sync.aligned.m8n8.x4.shared.b16 {%0,%1,%2,%3}, [%4];"
                 : "=r"(r[0]), "=r"(r[1]), "=r"(r[2]), "=r"(r[3]) : "r"(addr));
}

__device__ __forceinline__ void mma_bf16(float* d, const uint32_t* a, const uint32_t* b) {
    asm volatile("mma.sync.aligned.m16n8k16.row.col.f32.bf16.bf16.f32 "
                 "{%0,%1,%2,%3},{%4,%5,%6,%7},{%8,%9},{%0,%1,%2,%3};"
                 : "+f"(d[0]), "+f"(d[1]), "+f"(d[2]), "+f"(d[3])
                 : "r"(a[0]), "r"(a[1]), "r"(a[2]), "r"(a[3]), "r"(b[0]), "r"(b[1]));
}

// ---------------------------------------------------------------------------
// Weight convert: fp32 [300][300] -> bf16 [320][320] row-major, zero-padded
// ---------------------------------------------------------------------------
__global__ __launch_bounds__(256) void convert_w(__nv_bfloat16* __restrict__ dst,
                                                 const float* __restrict__ src)
{
    const int idx = blockIdx.x * 256 + threadIdx.x;
    if (idx >= KPAD * KPAD) return;
    const int h = idx / KPAD;
    const int k = idx - h * KPAD;
    dst[idx] = __float2bfloat16((h < 300 && k < 300) ? src[h * 300 + k] : 0.f);
}

// ---------------------------------------------------------------------------
// Fused main kernel — 512 threads (16 warps)
// ---------------------------------------------------------------------------
__global__ __launch_bounds__(THREADS) void fused_kernel(
    const int* __restrict__ cen_ids,  const int* __restrict__ ctx_ids,
    const int* __restrict__ neg_ids,  const int* __restrict__ labels,
    const float* __restrict__ cen_emb, const float* __restrict__ ctx_emb,
    const float* __restrict__ b_enc,  const float* __restrict__ b_dec,
    const float* __restrict__ W_cls,  const float* __restrict__ b_cls)
{
    extern __shared__ char smc[];
    float* smf = (float*)smc;
    const uint32_t sb = smem_u32(smc);
    const int tid  = threadIdx.x;
    const int wid  = tid >> 5;          // 0..15
    const int lane = tid & 31;
    const int r0   = blockIdx.x * ROWS;

    // ---- Phase 0: constants + gather emb -> bf16 A tile ----
    for (int i = tid; i < 640; i += THREADS) {
        const int cls = i / KPAD, col = i - cls * KPAD;
        smf[SMF_WCLS + i] = (col < 300) ? W_cls[cls * 300 + col] : 0.f;
    }
    for (int i = tid; i < KPAD; i += THREADS) {
        smf[SMF_BENC + i] = (i < 300) ? b_enc[i] : 0.f;
        smf[SMF_BDEC + i] = (i < 300) ? b_dec[i] : 0.f;
    }
    for (int idx = tid; idx < ROWS * (KPAD / 2); idx += THREADS) {
        const int r = idx / (KPAD / 2);
        const int c = (idx - r * (KPAD / 2)) * 2;
        float2 v = make_float2(0.f, 0.f);
        if (c < 300)
            v = *(const float2*)(cen_emb + (size_t)cen_ids[r0 + r] * EMBED + c);
        *(__nv_bfloat162*)(smc + SMB_A + r * ROWB + c * 2) = __floats2bfloat162_rn(v.x, v.y);
    }
    __syncthreads();

    // GEMM warp mapping: 8 m-groups x 2 n-halves
    const int mg    = wid & 7;
    const int nhalf = wid >> 3;
    const int m0    = mg * 16;
    const int rowA  = m0 + (lane >> 2);         // second row = rowA + 8
    const int cq    = (lane & 3) * 2;
    float lg00 = 0.f, lg01 = 0.f, lg10 = 0.f, lg11 = 0.f;

    // ================= two chained GEMMs =================
    #pragma unroll 1
    for (int g = 0; g < 2; ++g) {
        const __nv_bfloat16* gW = g ? g_Wdec : g_Wenc;
        const uint32_t aBase = sb + (g ? SMB_A2 : SMB_A);
        const uint32_t aAddr0 = aBase + (uint32_t)(m0 + (lane & 15)) * ROWB
                              + (uint32_t)((lane >> 4) * 8) * 2;
        const uint32_t bAddr0 = sb + SMB_B
                              + (uint32_t)(nhalf * 32 + ((lane >> 4) << 3) + (lane & 7)) * ROWB
                              + (uint32_t)(((lane >> 3) & 1) * 8) * 2;

        #pragma unroll 1
        for (int chunk = 0; chunk < 5; ++chunk) {
            const int n0 = chunk * 64;
            // ---- stream B chunk: W rows n0..n0+63, 320 cols ----
            {
                const uint4* src = (const uint4*)(gW + (size_t)n0 * KPAD);
                for (int i = tid; i < 64 * 40; i += THREADS) {
                    const int r = i / 40, q = i - r * 40;
                    *(uint4*)(smc + SMB_B + r * ROWB + q * 16) = src[r * 40 + q];
                }
            }
            __syncthreads();

            float acc[4][4];
            #pragma unroll
            for (int j = 0; j < 4; ++j)
                #pragma unroll
                for (int i = 0; i < 4; ++i) acc[j][i] = 0.f;

            #pragma unroll 4
            for (int ks = 0; ks < 20; ++ks) {
                uint32_t a[4];
                ldsm_x4(a, aAddr0 + ks * 32);
                #pragma unroll
                for (int jt2 = 0; jt2 < 2; ++jt2) {
                    uint32_t b[4];
                    ldsm_x4(b, bAddr0 + jt2 * 16 * ROWB + ks * 32);
                    mma_bf16(acc[2 * jt2],     a, b);
                    mma_bf16(acc[2 * jt2 + 1], a, b + 2);
                }
            }

            // ---- epilogue for this chunk (in-register) ----
            if (g == 0) {
                #pragma unroll
                for (int j = 0; j < 4; ++j) {
                    const int c0 = n0 + nhalf * 32 + (j >> 1) * 16 + (j & 1) * 8 + cq;
                    const float be0 = smf[SMF_BENC + c0], be1 = smf[SMF_BENC + c0 + 1];
                    const float v0 = acc[j][0] + be0, v1 = acc[j][1] + be1;
                    const float v2 = acc[j][2] + be0, v3 = acc[j][3] + be1;
                    const float w00 = smf[SMF_WCLS + c0],       w01 = smf[SMF_WCLS + c0 + 1];
                    const float w10 = smf[SMF_WCLS + 320 + c0], w11 = smf[SMF_WCLS + 320 + c0 + 1];
                    lg00 += v0 * w00 + v1 * w01;  lg01 += v0 * w10 + v1 * w11;
                    lg10 += v2 * w00 + v3 * w01;  lg11 += v2 * w10 + v3 * w11;
                    *(__nv_bfloat162*)(smc + SMB_A2 + rowA * ROWB + c0 * 2) =
                        __floats2bfloat162_rn(v0, v1);
                    *(__nv_bfloat162*)(smc + SMB_A2 + (rowA + 8) * ROWB + c0 * 2) =
                        __floats2bfloat162_rn(v2, v3);
                }
            } else {
                #pragma unroll
                for (int j = 0; j < 4; ++j) {
                    const int c0 = n0 + nhalf * 32 + (j >> 1) * 16 + (j & 1) * 8 + cq;
                    const float bd0 = smf[SMF_BDEC + c0], bd1 = smf[SMF_BDEC + c0 + 1];
                    *(__nv_bfloat162*)(smc + SMB_A + rowA * ROWB + c0 * 2) =
                        __floats2bfloat162_rn(acc[j][0] + bd0, acc[j][1] + bd1);
                    *(__nv_bfloat162*)(smc + SMB_A + (rowA + 8) * ROWB + c0 * 2) =
                        __floats2bfloat162_rn(acc[j][2] + bd0, acc[j][3] + bd1);
                }
            }
            __syncthreads();
        }

        if (g == 0) {
            // quad-reduce logits partials (fixed order), stash per n-half
            lg00 += __shfl_xor_sync(0xffffffffu, lg00, 1);
            lg00 += __shfl_xor_sync(0xffffffffu, lg00, 2);
            lg01 += __shfl_xor_sync(0xffffffffu, lg01, 1);
            lg01 += __shfl_xor_sync(0xffffffffu, lg01, 2);
            lg10 += __shfl_xor_sync(0xffffffffu, lg10, 1);
            lg10 += __shfl_xor_sync(0xffffffffu, lg10, 2);
            lg11 += __shfl_xor_sync(0xffffffffu, lg11, 1);
            lg11 += __shfl_xor_sync(0xffffffffu, lg11, 2);
            if ((lane & 3) == 0) {
                const int base = nhalf ? SMF_LGQ : SMF_LGP;
                smf[base + rowA * 2]           = lg00;
                smf[base + rowA * 2 + 1]       = lg01;
                smf[base + (rowA + 8) * 2]     = lg10;
                smf[base + (rowA + 8) * 2 + 1] = lg11;
            }
            __syncthreads();
            if (tid < 128) {
                const float l0 = smf[SMF_LGP + tid * 2]     + smf[SMF_LGQ + tid * 2]     + b_cls[0];
                const float l1 = smf[SMF_LGP + tid * 2 + 1] + smf[SMF_LGQ + tid * 2 + 1] + b_cls[1];
                const float m  = fmaxf(l0, l1);
                const float lse = m + log1pf(__expf(fminf(l0, l1) - m));
                smf[SMF_NLL + tid] = lse - (labels[r0 + tid] ? l1 : l0);
            }
            // no sync needed: SMF_NLL only read after later barriers
        }
    }

    // ---- Phase 3: pos/neg dots vs gathered ctx_emb (cv bf16 in A region) ----
    const int o = lane >> 3;
    const int l = lane & 7;
    float accDeno = 0.f;

    #pragma unroll 1
    for (int t = 0; t < 8; ++t) {
        const int r  = wid * 8 + t;
        const int gr = r0 + r;
        const char* cvp = smc + SMB_A + r * ROWB;

        #pragma unroll
        for (int round = 0; round < 3; ++round) {
            const int j = round * 4 + o;
            const bool valid = (j < 11);
            int widx = 0;
            if (valid) widx = (j == 0) ? ctx_ids[gr] : neg_ids[gr * KNEG + (j - 1)];
            const float4* xp = (const float4*)(ctx_emb + (size_t)widx * EMBED);

            float acc = 0.f;
            #pragma unroll
            for (int s = 0; s < 10; ++s) {
                const int e4 = s * 8 + l;
                if (e4 < 75) {
                    const uint2 u = *(const uint2*)(cvp + e4 * 8);
                    const float2 p0 = __bfloat1622float2(*(const __nv_bfloat162*)&u.x);
                    const float2 p1 = __bfloat1622float2(*(const __nv_bfloat162*)&u.y);
                    const float4 x = xp[e4];
                    acc += p0.x * x.x + p0.y * x.y + p1.x * x.z + p1.y * x.w;
                }
            }
            acc += __shfl_down_sync(0xffffffffu, acc, 4, 8);
            acc += __shfl_down_sync(0xffffffffu, acc, 2, 8);
            acc += __shfl_down_sync(0xffffffffu, acc, 1, 8);

            if (l == 0 && valid) {
                const float s1 = fminf(fmaxf(acc, -10.f), 10.f);
                accDeno += (j == 0) ? log1pf(__expf(-s1)) : log1pf(__expf(s1));
            }
        }
    }
    if (l == 0) smf[SMF_DENO + wid * 4 + o] = accDeno;
    __syncthreads();

    // ---- fixed-order block reduction ----
    if (tid == 0) {
        float sd = 0.f, sn = 0.f;
        #pragma unroll
        for (int i = 0; i < 64;  ++i) sd += smf[SMF_DENO + i];
        #pragma unroll
        for (int i = 0; i < 128; ++i) sn += smf[SMF_NLL + i];
        g_partials[blockIdx.x] = make_float2(sd, sn);
    }
}

__global__ __launch_bounds__(256) void finalize_kernel(float* __restrict__ out)
{
    __shared__ float sd[256], sn[256];
    const int t = threadIdx.x;
    const float2 p = g_partials[t];
    sd[t] = p.x;  sn[t] = p.y;
    __syncthreads();
    for (int ofs = 128; ofs > 0; ofs >>= 1) {
        if (t < ofs) { sd[t] += sd[t + ofs]; sn[t] += sn[t + ofs]; }
        __syncthreads();
    }
    if (t == 0) {
        const float invB = 1.0f / (float)BATCH;
        float deno = fminf(fmaxf(sd[0] * invB, 1e-5f), 10.f);
        float cono = fminf(fmaxf(sn[0] * invB, 1e-5f), 10.f);
        out[0] = fmaxf(deno + cono, 1e-5f);
        out[1] = deno;
        out[2] = cono;
    }
}

extern "C" void kernel_launch(void* const* d_in, const int* in_sizes, int n_in,
                              void* d_out, int out_size)
{
    const int*   cen_ids = (const int*)  d_in[0];
    const int*   ctx_ids = (const int*)  d_in[1];
    const int*   neg_ids = (const int*)  d_in[2];
    const int*   labels  = (const int*)  d_in[3];
    const float* cen_emb = (const float*)d_in[4];
    const float* ctx_emb = (const float*)d_in[5];
    const float* W_enc   = (const float*)d_in[6];
    const float* b_enc   = (const float*)d_in[7];
    const float* W_dec   = (const float*)d_in[8];
    const float* b_dec   = (const float*)d_in[9];
    const float* W_cls   = (const float*)d_in[10];
    const float* b_cls   = (const float*)d_in[11];

    __nv_bfloat16* we;  cudaGetSymbolAddress((void**)&we, g_Wenc);
    __nv_bfloat16* wd;  cudaGetSymbolAddress((void**)&wd, g_Wdec);

    const int cBlocks = (KPAD * KPAD + 255) / 256;
    convert_w<<<cBlocks, 256>>>(we, W_enc);
    convert_w<<<cBlocks, 256>>>(wd, W_dec);

    cudaFuncSetAttribute(fused_kernel,
                         cudaFuncAttributeMaxDynamicSharedMemorySize, SM_TOTAL);
    fused_kernel<<<NBLK, THREADS, SM_TOTAL>>>(
        cen_ids, ctx_ids, neg_ids, labels, cen_emb, ctx_emb,
        b_enc, b_dec, W_cls, b_cls);
    finalize_kernel<<<1, 256>>>((float*)d_out);
}

// round 7
// speedup vs baseline: 7.5839x; 1.0051x over previous
#include <cuda_runtime.h>
#include <cuda_bf16.h>
#include <math.h>
#include <stdint.h>

#define BATCH   32768
#define ROWS    64
#define NBLK    (BATCH / ROWS)      // 512
#define EMBED   300
#define KNEG    10
#define KPAD    320
#define THREADS 256
#define ROWB    656                 // smem row pitch bytes (328 bf16): +16B bank rotation
#define BCHUNK  32                  // B rows per chunk
#define NCHUNK  10

// ---- smem float-index layout for misc block ----
#define SMF_NLL   0                  // 64
#define SMF_DENO  64                 // 32
#define SMF_WCLS  96                 // 640
#define SMF_BENC  736                // 320
#define SMF_BDEC  1056               // 320
#define SMF_LGP   1376               // 128 (nhalf=0 partial logits [64][2])
#define SMF_LGQ   1504               // 128 (nhalf=1)
// ---- smem byte layout ----
#define SMB_A     6656
#define SMB_A2    (SMB_A  + ROWS * ROWB)      // 48640
#define SMB_B     (SMB_A2 + ROWS * ROWB)      // 90624
#define SM_TOTAL  (SMB_B  + BCHUNK * ROWB)    // 111616 (~109 KB) -> 2 blocks/SM

__device__ __nv_bfloat16 g_Wenc[KPAD * KPAD];   // [h][k] row-major, zero padded
__device__ __nv_bfloat16 g_Wdec[KPAD * KPAD];
__device__ float2 g_partials[NBLK];

__device__ __forceinline__ uint32_t smem_u32(const void* p) {
    uint32_t a;
    asm("{ .reg .u64 t; cvta.to.shared.u64 t, %1; cvt.u32.u64 %0, t; }" : "=r"(a) : "l"(p));
    return a;
}

__device__ __forceinline__ void ldsm_x4(uint32_t* r, uint32_t addr) {
    asm volatile("ldmatrix.sync.aligned.m8n8.x4.shared.b16 {%0,%1,%2,%3}, [%4];"
                 : "=r"(r[0]), "=r"(r[1]), "=r"(r[2]), "=r"(r[3]) : "r"(addr));
}

__device__ __forceinline__ void mma_bf16(float* d, const uint32_t* a, const uint32_t* b) {
    asm volatile("mma.sync.aligned.m16n8k16.row.col.f32.bf16.bf16.f32 "
                 "{%0,%1,%2,%3},{%4,%5,%6,%7},{%8,%9},{%0,%1,%2,%3};"
                 : "+f"(d[0]), "+f"(d[1]), "+f"(d[2]), "+f"(d[3])
                 : "r"(a[0]), "r"(a[1]), "r"(a[2]), "r"(a[3]), "r"(b[0]), "r"(b[1]));
}

// ---------------------------------------------------------------------------
// Weight convert: fp32 [300][300] -> bf16 [320][320] row-major, zero-padded
// ---------------------------------------------------------------------------
__global__ __launch_bounds__(256) void convert_w(__nv_bfloat16* __restrict__ dst,
                                                 const float* __restrict__ src)
{
    const int idx = blockIdx.x * 256 + threadIdx.x;
    if (idx >= KPAD * KPAD) return;
    const int h = idx / KPAD;
    const int k = idx - h * KPAD;
    dst[idx] = __float2bfloat16((h < 300 && k < 300) ? src[h * 300 + k] : 0.f);
}

// ---------------------------------------------------------------------------
// Fused main kernel — 256 threads (8 warps), target 2 blocks/SM
// ---------------------------------------------------------------------------
__global__ __launch_bounds__(THREADS, 2) void fused_kernel(
    const int* __restrict__ cen_ids,  const int* __restrict__ ctx_ids,
    const int* __restrict__ neg_ids,  const int* __restrict__ labels,
    const float* __restrict__ cen_emb, const float* __restrict__ ctx_emb,
    const float* __restrict__ b_enc,  const float* __restrict__ b_dec,
    const float* __restrict__ W_cls,  const float* __restrict__ b_cls)
{
    extern __shared__ char smc[];
    float* smf = (float*)smc;
    const uint32_t sb = smem_u32(smc);
    const int tid  = threadIdx.x;
    const int wid  = tid >> 5;          // 0..7
    const int lane = tid & 31;
    const int r0   = blockIdx.x * ROWS;

    // ---- Phase 0: constants + gather emb -> bf16 A tile ----
    for (int i = tid; i < 640; i += THREADS) {
        const int cls = i / KPAD, col = i - cls * KPAD;
        smf[SMF_WCLS + i] = (col < 300) ? W_cls[cls * 300 + col] : 0.f;
    }
    for (int i = tid; i < KPAD; i += THREADS) {
        smf[SMF_BENC + i] = (i < 300) ? b_enc[i] : 0.f;
        smf[SMF_BDEC + i] = (i < 300) ? b_dec[i] : 0.f;
    }
    for (int idx = tid; idx < ROWS * (KPAD / 2); idx += THREADS) {
        const int r = idx / (KPAD / 2);
        const int c = (idx - r * (KPAD / 2)) * 2;
        float2 v = make_float2(0.f, 0.f);
        if (c < 300)
            v = *(const float2*)(cen_emb + (size_t)cen_ids[r0 + r] * EMBED + c);
        *(__nv_bfloat162*)(smc + SMB_A + r * ROWB + c * 2) = __floats2bfloat162_rn(v.x, v.y);
    }
    __syncthreads();

    // GEMM warp mapping: 4 m-groups (16 rows) x 2 n-halves (16 cols of 32-col chunk)
    const int mg    = wid & 3;
    const int nhalf = wid >> 2;
    const int m0    = mg * 16;
    const int rowA  = m0 + (lane >> 2);         // second row = rowA + 8
    const int cq    = (lane & 3) * 2;
    float lg00 = 0.f, lg01 = 0.f, lg10 = 0.f, lg11 = 0.f;

    // ================= two chained GEMMs =================
    #pragma unroll 1
    for (int g = 0; g < 2; ++g) {
        const __nv_bfloat16* gW = g ? g_Wdec : g_Wenc;
        const uint32_t aBase = sb + (g ? SMB_A2 : SMB_A);
        const uint32_t aAddr0 = aBase + (uint32_t)(m0 + (lane & 15)) * ROWB
                              + (uint32_t)((lane >> 4) * 8) * 2;
        const uint32_t bAddr0 = sb + SMB_B
                              + (uint32_t)(nhalf * 16 + ((lane >> 4) << 3) + (lane & 7)) * ROWB
                              + (uint32_t)(((lane >> 3) & 1) * 8) * 2;

        #pragma unroll 1
        for (int chunk = 0; chunk < NCHUNK; ++chunk) {
            const int n0 = chunk * BCHUNK;
            // ---- stream B chunk: W rows n0..n0+31, 320 cols ----
            {
                const uint4* src = (const uint4*)(gW + (size_t)n0 * KPAD);
                for (int i = tid; i < BCHUNK * 20; i += THREADS) {
                    const int r = i / 20, q = (i - r * 20) * 2;
                    *(uint4*)(smc + SMB_B + r * ROWB + q * 16)        = src[r * 40 + q];
                    *(uint4*)(smc + SMB_B + r * ROWB + (q + 1) * 16)  = src[r * 40 + q + 1];
                }
            }
            __syncthreads();

            float acc[2][4];
            #pragma unroll
            for (int j = 0; j < 2; ++j)
                #pragma unroll
                for (int i = 0; i < 4; ++i) acc[j][i] = 0.f;

            #pragma unroll 5
            for (int ks = 0; ks < 20; ++ks) {
                uint32_t a[4], b[4];
                ldsm_x4(a, aAddr0 + ks * 32);
                ldsm_x4(b, bAddr0 + ks * 32);
                mma_bf16(acc[0], a, b);
                mma_bf16(acc[1], a, b + 2);
            }

            // ---- epilogue for this chunk (in-register) ----
            if (g == 0) {
                #pragma unroll
                for (int j = 0; j < 2; ++j) {
                    const int c0 = n0 + nhalf * 16 + j * 8 + cq;
                    const float be0 = smf[SMF_BENC + c0], be1 = smf[SMF_BENC + c0 + 1];
                    const float v0 = acc[j][0] + be0, v1 = acc[j][1] + be1;
                    const float v2 = acc[j][2] + be0, v3 = acc[j][3] + be1;
                    const float w00 = smf[SMF_WCLS + c0],       w01 = smf[SMF_WCLS + c0 + 1];
                    const float w10 = smf[SMF_WCLS + 320 + c0], w11 = smf[SMF_WCLS + 320 + c0 + 1];
                    lg00 += v0 * w00 + v1 * w01;  lg01 += v0 * w10 + v1 * w11;
                    lg10 += v2 * w00 + v3 * w01;  lg11 += v2 * w10 + v3 * w11;
                    *(__nv_bfloat162*)(smc + SMB_A2 + rowA * ROWB + c0 * 2) =
                        __floats2bfloat162_rn(v0, v1);
                    *(__nv_bfloat162*)(smc + SMB_A2 + (rowA + 8) * ROWB + c0 * 2) =
                        __floats2bfloat162_rn(v2, v3);
                }
            } else {
                #pragma unroll
                for (int j = 0; j < 2; ++j) {
                    const int c0 = n0 + nhalf * 16 + j * 8 + cq;
                    const float bd0 = smf[SMF_BDEC + c0], bd1 = smf[SMF_BDEC + c0 + 1];
                    *(__nv_bfloat162*)(smc + SMB_A + rowA * ROWB + c0 * 2) =
                        __floats2bfloat162_rn(acc[j][0] + bd0, acc[j][1] + bd1);
                    *(__nv_bfloat162*)(smc + SMB_A + (rowA + 8) * ROWB + c0 * 2) =
                        __floats2bfloat162_rn(acc[j][2] + bd0, acc[j][3] + bd1);
                }
            }
            __syncthreads();
        }

        if (g == 0) {
            // quad-reduce logits partials (fixed order), stash per n-half
            lg00 += __shfl_xor_sync(0xffffffffu, lg00, 1);
            lg00 += __shfl_xor_sync(0xffffffffu, lg00, 2);
            lg01 += __shfl_xor_sync(0xffffffffu, lg01, 1);
            lg01 += __shfl_xor_sync(0xffffffffu, lg01, 2);
            lg10 += __shfl_xor_sync(0xffffffffu, lg10, 1);
            lg10 += __shfl_xor_sync(0xffffffffu, lg10, 2);
            lg11 += __shfl_xor_sync(0xffffffffu, lg11, 1);
            lg11 += __shfl_xor_sync(0xffffffffu, lg11, 2);
            if ((lane & 3) == 0) {
                const int base = nhalf ? SMF_LGQ : SMF_LGP;
                smf[base + rowA * 2]           = lg00;
                smf[base + rowA * 2 + 1]       = lg01;
                smf[base + (rowA + 8) * 2]     = lg10;
                smf[base + (rowA + 8) * 2 + 1] = lg11;
            }
            __syncthreads();
            if (tid < ROWS) {
                const float l0 = smf[SMF_LGP + tid * 2]     + smf[SMF_LGQ + tid * 2]     + b_cls[0];
                const float l1 = smf[SMF_LGP + tid * 2 + 1] + smf[SMF_LGQ + tid * 2 + 1] + b_cls[1];
                const float m  = fmaxf(l0, l1);
                const float lse = m + log1pf(__expf(fminf(l0, l1) - m));
                smf[SMF_NLL + tid] = lse - (labels[r0 + tid] ? l1 : l0);
            }
            // no sync needed: SMF_NLL only read after later barriers
        }
    }

    // ---- Phase 3: pos/neg dots vs gathered ctx_emb (cv bf16 in A region) ----
    const int o = lane >> 3;
    const int l = lane & 7;
    float accDeno = 0.f;

    #pragma unroll 1
    for (int t = 0; t < 8; ++t) {
        const int r  = wid * 8 + t;
        const int gr = r0 + r;
        const char* cvp = smc + SMB_A + r * ROWB;

        #pragma unroll
        for (int round = 0; round < 3; ++round) {
            const int j = round * 4 + o;
            const bool valid = (j < 11);
            int widx = 0;
            if (valid) widx = (j == 0) ? ctx_ids[gr] : neg_ids[gr * KNEG + (j - 1)];
            const float4* xp = (const float4*)(ctx_emb + (size_t)widx * EMBED);

            float acc = 0.f;
            #pragma unroll
            for (int s = 0; s < 10; ++s) {
                const int e4 = s * 8 + l;
                if (e4 < 75) {
                    const uint2 u = *(const uint2*)(cvp + e4 * 8);
                    const float2 p0 = __bfloat1622float2(*(const __nv_bfloat162*)&u.x);
                    const float2 p1 = __bfloat1622float2(*(const __nv_bfloat162*)&u.y);
                    const float4 x = xp[e4];
                    acc += p0.x * x.x + p0.y * x.y + p1.x * x.z + p1.y * x.w;
                }
            }
            acc += __shfl_down_sync(0xffffffffu, acc, 4, 8);
            acc += __shfl_down_sync(0xffffffffu, acc, 2, 8);
            acc += __shfl_down_sync(0xffffffffu, acc, 1, 8);

            if (l == 0 && valid) {
                const float s1 = fminf(fmaxf(acc, -10.f), 10.f);
                accDeno += (j == 0) ? log1pf(__expf(-s1)) : log1pf(__expf(s1));
            }
        }
    }
    if (l == 0) smf[SMF_DENO + wid * 4 + o] = accDeno;
    __syncthreads();

    // ---- fixed-order block reduction ----
    if (tid == 0) {
        float sd = 0.f, sn = 0.f;
        #pragma unroll
        for (int i = 0; i < 32; ++i) sd += smf[SMF_DENO + i];
        #pragma unroll
        for (int i = 0; i < ROWS; ++i) sn += smf[SMF_NLL + i];
        g_partials[blockIdx.x] = make_float2(sd, sn);
    }
}

__global__ __launch_bounds__(256) void finalize_kernel(float* __restrict__ out)
{
    __shared__ float sd[256], sn[256];
    const int t = threadIdx.x;
    const float2 p0 = g_partials[t];
    const float2 p1 = g_partials[t + 256];
    sd[t] = p0.x + p1.x;
    sn[t] = p0.y + p1.y;
    __syncthreads();
    for (int ofs = 128; ofs > 0; ofs >>= 1) {
        if (t < ofs) { sd[t] += sd[t + ofs]; sn[t] += sn[t + ofs]; }
        __syncthreads();
    }
    if (t == 0) {
        const float invB = 1.0f / (float)BATCH;
        float deno = fminf(fmaxf(sd[0] * invB, 1e-5f), 10.f);
        float cono = fminf(fmaxf(sn[0] * invB, 1e-5f), 10.f);
        out[0] = fmaxf(deno + cono, 1e-5f);
        out[1] = deno;
        out[2] = cono;
    }
}

extern "C" void kernel_launch(void* const* d_in, const int* in_sizes, int n_in,
                              void* d_out, int out_size)
{
    const int*   cen_ids = (const int*)  d_in[0];
    const int*   ctx_ids = (const int*)  d_in[1];
    const int*   neg_ids = (const int*)  d_in[2];
    const int*   labels  = (const int*)  d_in[3];
    const float* cen_emb = (const float*)d_in[4];
    const float* ctx_emb = (const float*)d_in[5];
    const float* W_enc   = (const float*)d_in[6];
    const float* b_enc   = (const float*)d_in[7];
    const float* W_dec   = (const float*)d_in[8];
    const float* b_dec   = (const float*)d_in[9];
    const float* W_cls   = (const float*)d_in[10];
    const float* b_cls   = (const float*)d_in[11];

    __nv_bfloat16* we;  cudaGetSymbolAddress((void**)&we, g_Wenc);
    __nv_bfloat16* wd;  cudaGetSymbolAddress((void**)&wd, g_Wdec);

    const int cBlocks = (KPAD * KPAD + 255) / 256;
    convert_w<<<cBlocks, 256>>>(we, W_enc);
    convert_w<<<cBlocks, 256>>>(wd, W_dec);

    cudaFuncSetAttribute(fused_kernel,
                         cudaFuncAttributeMaxDynamicSharedMemorySize, SM_TOTAL);
    fused_kernel<<<NBLK, THREADS, SM_TOTAL>>>(
        cen_ids, ctx_ids, neg_ids, labels, cen_emb, ctx_emb,
        b_enc, b_dec, W_cls, b_cls);
    finalize_kernel<<<1, 256>>>((float*)d_out);
}